// round 12
// baseline (speedup 1.0000x reference)
#include <cuda_runtime.h>
#include <cuda_bf16.h>

// RKN scan R12: R11 structure scaled to 512 threads / 4 groups (1-2 diagonals
// each), 4 warps per SMSP for latency hiding. g1/g2 keep tables in registers;
// g0 (fp32 diag) and g3 (d5,d6 bf16) stream from smem. rcp.approx divisions.

#define NB   128
#define NT   128
#define NLOD 128
#define NK   16

// dynamic smem layout (bytes)
static constexpr int DG_OFF  = 0;                        // float4[NK*NLOD] diag fp32
static constexpr int OD_OFF  = DG_OFF + NK * NLOD * 16;  // uint4[NK*NLOD] d5,d6
static constexpr int ST_OFF  = OD_OFF + NK * NLOD * 16;  // float4[136] state
static constexpr int CS_OFF  = ST_OFF + 136 * 16;        // float[136]
static constexpr int RED_OFF = CS_OFF + 136 * 4;         // float[64]
static constexpr int P4_OFF  = RED_OFF + 64 * 4;         // float4[4][128]
static constexpr int P1_OFF  = P4_OFF + 4 * 128 * 16;    // float[4][128]
static constexpr int SMEM_BYTES = P1_OFF + 4 * 128 * 4;  // ~78 KB

__device__ __forceinline__ unsigned int pk(float a, float b) {
    __nv_bfloat162 t = __floats2bfloat162_rn(a, b);
    return reinterpret_cast<unsigned int&>(t);
}
// acc(f32x2) += { lo: p<<16 (exact), hi: raw p (garbage low mantissa) } * {a,a}
__device__ __forceinline__ void pair_fma(unsigned long long& acc,
                                         unsigned int p, unsigned long long a2) {
    asm("{\n\t.reg .b32 lo;\n\t.reg .b64 v;\n\t"
        "shl.b32 lo, %1, 16;\n\t"
        "mov.b64 v, {lo, %1};\n\t"
        "fma.rn.f32x2 %0, v, %2, %0;\n\t}"
        : "+l"(acc) : "r"(p), "l"(a2));
}
__device__ __forceinline__ unsigned long long dup2(float a) {
    unsigned long long r;
    asm("mov.b64 %0, {%1, %1};" : "=l"(r) : "f"(a));
    return r;
}
__device__ __forceinline__ void unpk2(unsigned long long r, float& x, float& y) {
    asm("mov.b64 {%0, %1}, %2;" : "=f"(x), "=f"(y) : "l"(r));
}
__device__ __forceinline__ float frcp(float x) {
    float r;
    asm("rcp.approx.f32 %0, %1;" : "=f"(r) : "f"(x));
    return r;
}

#define RED_ROUND(m)                                                          \
  _Pragma("unroll")                                                           \
  for (int k = 0; k < (m); k++) {                                             \
    float a_ = v[k], c_ = v[k + (m)];                                         \
    bool  hi_ = (lane & (m)) != 0;                                            \
    float keep_ = hi_ ? c_ : a_;                                              \
    float send_ = hi_ ? a_ : c_;                                              \
    v[k] = keep_ + __shfl_xor_sync(0xffffffffu, send_, (m));                  \
  }

// normalize by inv, then accumulate one diagonal's matvec contribution
#define BAND_NORM_ACC(d, A11, A12, A21, A22)                                  \
  {                                                                           \
    float a11 = (A11) * inv, a12 = (A12) * inv;                               \
    float a21 = (A21) * inv, a22 = (A22) * inv;                               \
    float4 st_ = s_st[i + (d)];                                               \
    float  csj = s_cs[i + (d)];                                               \
    float muj = st_.x, mlj = st_.y, cuj = st_.z, clj = st_.w;                 \
    nmu = fmaf(a11, muj, nmu); nmu = fmaf(a12, mlj, nmu);                     \
    nml = fmaf(a21, muj, nml); nml = fmaf(a22, mlj, nml);                     \
    ncu = fmaf(a11 * a11, cuj, ncu);                                          \
    ncu = fmaf(2.0f * a11 * a12, csj, ncu);                                   \
    ncu = fmaf(a12 * a12, clj, ncu);                                          \
    ncl = fmaf(a21 * a21, cuj, ncl);                                          \
    ncl = fmaf(2.0f * a21 * a22, csj, ncl);                                   \
    ncl = fmaf(a22 * a22, clj, ncl);                                          \
    ncs = fmaf(a21 * a11, cuj, ncs);                                          \
    ncs = fmaf(fmaf(a22, a11, a21 * a12), csj, ncs);                          \
    ncs = fmaf(a22 * a12, clj, ncs);                                          \
  }

__global__ void __launch_bounds__(512, 1)
rkn_kernel(const float* __restrict__ lobs,   // (B,T,LOD)
           const float* __restrict__ ovars,  // (B,T,LOD)
           const float* __restrict__ imean,  // (B,2*LOD)
           const float* __restrict__ icu,
           const float* __restrict__ icl,
           const float* __restrict__ ics,
           const float* __restrict__ tm11,   // (K,LOD,LOD)
           const float* __restrict__ tm12,
           const float* __restrict__ tm21,
           const float* __restrict__ tm22,
           const float* __restrict__ cw,     // (2*LOD, K)
           const float* __restrict__ cb,     // (K,)
           const float* __restrict__ tcu,
           const float* __restrict__ tcl,
           float* __restrict__ out)
{
    extern __shared__ char smraw[];
    float4* dg   = reinterpret_cast<float4*>(smraw + DG_OFF);
    uint4*  od   = reinterpret_cast<uint4*>(smraw + OD_OFF);
    float4* s_st = reinterpret_cast<float4*>(smraw + ST_OFF);   // [136]
    float*  s_cs = reinterpret_cast<float*>(smraw + CS_OFF);    // [136]
    float*  red  = reinterpret_cast<float*>(smraw + RED_OFF);   // [64]
    float4* p4s  = reinterpret_cast<float4*>(smraw + P4_OFF);   // [4][128]
    float*  p1s  = reinterpret_cast<float*>(smraw + P1_OFF);    // [4][128]

    const int b    = blockIdx.x;
    const int tid  = threadIdx.x;
    const int lane = tid & 31;
    const int warp = tid >> 5;
    const int i    = tid & 127;   // row
    const int g    = tid >> 7;    // group 0..3
    const int k0g  = g << 2;      // this group's 4 logit k's

    // ---- prologue: smem tables ----
    for (int r = tid; r < NK * NLOD; r += 512) {
        int k = r >> 7, ii = r & 127;
        long base = ((long)k * NLOD + ii) * NLOD;
        dg[r] = make_float4(__ldg(tm11 + base + ii), __ldg(tm12 + base + ii),
                            __ldg(tm21 + base + ii), __ldg(tm22 + base + ii));
        int j5 = ii + 2, j6 = ii + 3;
        float e11 = 0.f, e12 = 0.f, e21 = 0.f, e22 = 0.f;
        float f11 = 0.f, f12 = 0.f, f21 = 0.f, f22 = 0.f;
        if (j5 < NLOD) {
            e11 = __ldg(tm11 + base + j5); e12 = __ldg(tm12 + base + j5);
            e21 = __ldg(tm21 + base + j5); e22 = __ldg(tm22 + base + j5);
        }
        if (j6 < NLOD) {
            f11 = __ldg(tm11 + base + j6); f12 = __ldg(tm12 + base + j6);
            f21 = __ldg(tm21 + base + j6); f22 = __ldg(tm22 + base + j6);
        }
        od[r] = make_uint4(pk(e11, e12), pk(e21, e22),
                           pk(f11, f12), pk(f21, f22));
    }
    for (int idx = tid; idx < 136; idx += 512) {
        s_st[idx] = make_float4(0.f, 0.f, 0.f, 0.f);
        s_cs[idx] = 0.f;
    }

    const float bbl  = __ldg(cb + (lane & 15));
    const float tcur = __ldg(tcu + i);
    const float tclr = __ldg(tcl + i);

    // this group's 4 softmax-weight columns for row i
    float Wu[4], Wl[4];
    #pragma unroll
    for (int kk = 0; kk < 4; kk++) {
        Wu[kk] = __ldg(cw + i * NK + k0g + kk);
        Wl[kk] = __ldg(cw + (NLOD + i) * NK + k0g + kk);
    }

    // carry partial (registers) + smem mirror; g0 seeds with initial state
    float cmu, cml, ccu, ccl, ccs;
    if (g == 0) {
        cmu = imean[(long)b * 2 * NLOD + i];
        cml = imean[(long)b * 2 * NLOD + NLOD + i];
        ccu = icu[(long)b * NLOD + i] - tcur;
        ccl = icl[(long)b * NLOD + i] - tclr;
        ccs = ics[(long)b * NLOD + i];
    } else {
        cmu = 0.f; cml = 0.f; ccu = 0.f; ccl = 0.f; ccs = 0.f;
    }
    p4s[g * 128 + i] = make_float4(cmu, cml, ccu, ccl);
    p1s[g * 128 + i] = ccs;

    const float* obs_p = lobs  + ((long)b * NT) * NLOD + i;
    const float* ov_p  = ovars + ((long)b * NT) * NLOD + i;
    float obs_r = __ldg(obs_p);
    float ov_r  = __ldg(ov_p);

    // ---- register tables (g1: d0,d1 ; g2: d2,d4). g0/g3 use smem. ----
    uint4 Ra[NK];
    if (g == 1 || g == 2) {
        const int ja = (g == 1) ? i - 3 : i - 1;
        const int jb = (g == 1) ? i - 2 : i + 1;
        const bool va = (unsigned)ja < (unsigned)NLOD;
        const bool vb = (unsigned)jb < (unsigned)NLOD;
        #pragma unroll
        for (int k = 0; k < NK; k++) {
            long base = ((long)k * NLOD + i) * NLOD;
            float a11 = 0.f, a12 = 0.f, a21 = 0.f, a22 = 0.f;
            float c11 = 0.f, c12 = 0.f, c21 = 0.f, c22 = 0.f;
            if (va) {
                a11 = __ldg(tm11 + base + ja); a12 = __ldg(tm12 + base + ja);
                a21 = __ldg(tm21 + base + ja); a22 = __ldg(tm22 + base + ja);
            }
            if (vb) {
                c11 = __ldg(tm11 + base + jb); c12 = __ldg(tm12 + base + jb);
                c21 = __ldg(tm21 + base + jb); c22 = __ldg(tm22 + base + jb);
            }
            Ra[k] = make_uint4(pk(a11, a12), pk(a21, a22),
                               pk(c11, c12), pk(c21, c22));
        }
    }

    float* out_pm = out;
    float* out_cu = out + (long)NB * NT * 2 * NLOD;
    float* out_cl = out_cu + (long)NB * NT * NLOD;
    float* out_cs = out_cl + (long)NB * NT * NLOD;

    __syncthreads();

    for (int t = 0; t < NT; t++) {
        // ========= phase 1 (all groups, redundant obs update) =========
        // combine: own carry (regs) + 3 other groups' partials
        const int g1i = ((g + 1) & 3) * 128 + i;
        const int g2i = ((g + 2) & 3) * 128 + i;
        const int g3i = ((g + 3) & 3) * 128 + i;
        float4 pa = p4s[g1i], pb = p4s[g2i], pc = p4s[g3i];
        float  sa = p1s[g1i], sb = p1s[g2i], sc = p1s[g3i];
        float pmU = (cmu + pa.x) + (pb.x + pc.x);
        float pmL = (cml + pa.y) + (pb.y + pc.y);
        float cU  = ((ccu + pa.z) + (pb.z + pc.z)) + tcur;
        float cL  = ((ccl + pa.w) + (pb.w + pc.w)) + tclr;
        float cS  = (ccs + sa) + (sb + sc);

        float rd    = frcp(cU + ov_r);
        float qu    = cU * rd;
        float ql    = cS * rd;
        float res   = obs_r - pmU;
        float pu    = pmU + qu * res;
        float pl    = pmL + ql * res;
        float cf    = 1.0f - qu;
        float pcu   = cf * cU;
        float pcl   = cL - ql * cS;
        float pcs   = cf * cS;

        if (t + 1 < NT) {
            obs_r = __ldg(obs_p + (t + 1) * NLOD);
            ov_r  = __ldg(ov_p  + (t + 1) * NLOD);
        }

        if (g == 0) {
            s_st[3 + i] = make_float4(pu, pl, pcu, pcl);
            s_cs[3 + i] = pcs;
        }

        // logits for this group's 4 k's, reduced over 128 rows
        float v[4];
        #pragma unroll
        for (int kk = 0; kk < 4; kk++) v[kk] = fmaf(pu, Wu[kk], pl * Wl[kk]);
        #pragma unroll
        for (int kk = 0; kk < 4; kk++) v[kk] += __shfl_xor_sync(0xffffffffu, v[kk], 16);
        RED_ROUND(2)
        RED_ROUND(1)
        v[0] += __shfl_xor_sync(0xffffffffu, v[0], 4);
        v[0] += __shfl_xor_sync(0xffffffffu, v[0], 8);
        if (lane < 4) red[(k0g + lane) * 4 + (warp & 3)] = v[0];

        // outputs (off critical path; split across groups)
        long obase = (long)b * NT + t;
        if (g == 0) {
            out_pm[obase * 2 * NLOD + i]        = pu;
            out_pm[obase * 2 * NLOD + NLOD + i] = pl;
        } else if (g == 1) {
            out_cu[obase * NLOD + i] = pcu;
        } else if (g == 2) {
            out_cl[obase * NLOD + i] = pcl;
        } else {
            out_cs[obase * NLOD + i] = pcs;
        }
        __syncthreads();   // B1

        // ========= phase 2: softmax (deferred norm) + A-gen + matvec =========
        float w_, s_;
        {
            const float4* red4 = reinterpret_cast<const float4*>(red);
            float4 rp = red4[lane & 15];
            float lg = bbl + ((rp.x + rp.y) + (rp.z + rp.w));
            w_ = __expf(lg);       // unnormalized weight for k = lane&15
            s_ = w_;
            #pragma unroll
            for (int m = 8; m >= 1; m >>= 1)
                s_ += __shfl_xor_sync(0xffffffffu, s_, m);
        }

        float nmu = 0.f, nml = 0.f, ncu = 0.f, ncl = 0.f, ncs = 0.f;

        if (g == 0) {
            // fp32 diagonal from smem
            float D11 = 0.f, D12 = 0.f, D21 = 0.f, D22 = 0.f;
            #pragma unroll
            for (int k = 0; k < NK; k++) {
                float a = __shfl_sync(0xffffffffu, w_, k);
                float4 gv = dg[k * NLOD + i];
                D11 = fmaf(a, gv.x, D11);
                D12 = fmaf(a, gv.y, D12);
                D21 = fmaf(a, gv.z, D21);
                D22 = fmaf(a, gv.w, D22);
            }
            const float inv = frcp(s_);
            float a11 = fmaf(D11, inv, 1.0f), a12 = D12 * inv;
            float a21 = D21 * inv, a22 = fmaf(D22, inv, 1.0f);
            float4 st_ = s_st[i + 3];
            float  csj = s_cs[i + 3];
            float muj = st_.x, mlj = st_.y, cuj = st_.z, clj = st_.w;
            nmu = fmaf(a11, muj, nmu); nmu = fmaf(a12, mlj, nmu);
            nml = fmaf(a21, muj, nml); nml = fmaf(a22, mlj, nml);
            ncu = fmaf(a11 * a11, cuj, ncu);
            ncu = fmaf(2.0f * a11 * a12, csj, ncu);
            ncu = fmaf(a12 * a12, clj, ncu);
            ncl = fmaf(a21 * a21, cuj, ncl);
            ncl = fmaf(2.0f * a21 * a22, csj, ncl);
            ncl = fmaf(a22 * a22, clj, ncl);
            ncs = fmaf(a21 * a11, cuj, ncs);
            ncs = fmaf(fmaf(a22, a11, a21 * a12), csj, ncs);
            ncs = fmaf(a22 * a12, clj, ncs);
        } else if (g == 3) {
            // d5,d6 bf16 streamed from smem
            unsigned long long P5 = 0ull, Q5 = 0ull, P6 = 0ull, Q6 = 0ull;
            #pragma unroll
            for (int k = 0; k < NK; k++) {
                unsigned long long a2 = dup2(__shfl_sync(0xffffffffu, w_, k));
                uint4 ro = od[k * NLOD + i];
                pair_fma(P5, ro.x, a2);
                pair_fma(Q5, ro.y, a2);
                pair_fma(P6, ro.z, a2);
                pair_fma(Q6, ro.w, a2);
            }
            const float inv = frcp(s_);
            float x, y, z, w2;
            unpk2(P5, x, y); unpk2(Q5, z, w2);
            BAND_NORM_ACC(5, x, y, z, w2)
            unpk2(P6, x, y); unpk2(Q6, z, w2);
            BAND_NORM_ACC(6, x, y, z, w2)
        } else {
            // g1: d0,d1 / g2: d2,d4 from registers
            unsigned long long Pa = 0ull, Qa = 0ull, Pb = 0ull, Qb = 0ull;
            #pragma unroll
            for (int k = 0; k < NK; k++) {
                unsigned long long a2 = dup2(__shfl_sync(0xffffffffu, w_, k));
                uint4 r = Ra[k];
                pair_fma(Pa, r.x, a2);
                pair_fma(Qa, r.y, a2);
                pair_fma(Pb, r.z, a2);
                pair_fma(Qb, r.w, a2);
            }
            const float inv = frcp(s_);
            float x, y, z, w2;
            if (g == 1) {
                unpk2(Pa, x, y); unpk2(Qa, z, w2);
                BAND_NORM_ACC(0, x, y, z, w2)
                unpk2(Pb, x, y); unpk2(Qb, z, w2);
                BAND_NORM_ACC(1, x, y, z, w2)
            } else {
                unpk2(Pa, x, y); unpk2(Qa, z, w2);
                BAND_NORM_ACC(2, x, y, z, w2)
                unpk2(Pb, x, y); unpk2(Qb, z, w2);
                BAND_NORM_ACC(4, x, y, z, w2)
            }
        }

        cmu = nmu; cml = nml; ccu = ncu; ccl = ncl; ccs = ncs;
        p4s[g * 128 + i] = make_float4(nmu, nml, ncu, ncl);
        p1s[g * 128 + i] = ncs;
        __syncthreads();   // B2
    }
}

extern "C" void kernel_launch(void* const* d_in, const int* in_sizes, int n_in,
                              void* d_out, int out_size)
{
    (void)in_sizes; (void)n_in; (void)out_size;
    const float* lobs  = (const float*)d_in[0];
    const float* ovars = (const float*)d_in[1];
    const float* imean = (const float*)d_in[2];
    const float* icu   = (const float*)d_in[3];
    const float* icl   = (const float*)d_in[4];
    const float* ics   = (const float*)d_in[5];
    const float* tm11  = (const float*)d_in[6];
    const float* tm12  = (const float*)d_in[7];
    const float* tm21  = (const float*)d_in[8];
    const float* tm22  = (const float*)d_in[9];
    const float* cw    = (const float*)d_in[10];
    const float* cb    = (const float*)d_in[11];
    const float* tcu   = (const float*)d_in[12];
    const float* tcl   = (const float*)d_in[13];
    float* out = (float*)d_out;

    cudaFuncSetAttribute(rkn_kernel,
                         cudaFuncAttributeMaxDynamicSharedMemorySize, SMEM_BYTES);

    rkn_kernel<<<NB, 512, SMEM_BYTES>>>(lobs, ovars, imean, icu, icl, ics,
                                        tm11, tm12, tm21, tm22,
                                        cw, cb, tcu, tcl, out);
}

// round 14
// speedup vs baseline: 2.1732x; 2.1732x over previous
#include <cuda_runtime.h>
#include <cuda_bf16.h>

// RKN scan R13/R14: R11 (best, 158us) + 9-shfl logit tree (value-split first),
// rcp.approx divisions, pointer-increment prefetch. 256 thr, 2 halves,
// 2 diagonals in regs per half, dg/od streamed from smem, 2 barriers/step.

#define NB   128
#define NT   128
#define NLOD 128
#define NK   16

// dynamic smem layout (bytes)
static constexpr int DG_OFF  = 0;                        // float4[NK*NLOD] diag fp32
static constexpr int OD_OFF  = DG_OFF + NK * NLOD * 16;  // uint4[NK*NLOD] d5,d6
static constexpr int ST_OFF  = OD_OFF + NK * NLOD * 16;  // float4[136] state
static constexpr int CS_OFF  = ST_OFF + 136 * 16;        // float[136]
static constexpr int RED_OFF = CS_OFF + 136 * 4;         // float[64]
static constexpr int P4_OFF  = RED_OFF + 64 * 4;         // float4[2][128]
static constexpr int P1_OFF  = P4_OFF + 2 * 128 * 16;    // float[2][128]
static constexpr int SMEM_BYTES = P1_OFF + 2 * 128 * 4;  // ~73.6 KB

__device__ __forceinline__ unsigned int pk(float a, float b) {
    __nv_bfloat162 t = __floats2bfloat162_rn(a, b);
    return reinterpret_cast<unsigned int&>(t);
}
// acc(f32x2) += { lo: p<<16 (exact), hi: raw p (garbage low mantissa) } * {a,a}
__device__ __forceinline__ void pair_fma(unsigned long long& acc,
                                         unsigned int p, unsigned long long a2) {
    asm("{\n\t.reg .b32 lo;\n\t.reg .b64 v;\n\t"
        "shl.b32 lo, %1, 16;\n\t"
        "mov.b64 v, {lo, %1};\n\t"
        "fma.rn.f32x2 %0, v, %2, %0;\n\t}"
        : "+l"(acc) : "r"(p), "l"(a2));
}
__device__ __forceinline__ unsigned long long dup2(float a) {
    unsigned long long r;
    asm("mov.b64 %0, {%1, %1};" : "=l"(r) : "f"(a));
    return r;
}
__device__ __forceinline__ void unpk2(unsigned long long r, float& x, float& y) {
    asm("mov.b64 {%0, %1}, %2;" : "=f"(x), "=f"(y) : "l"(r));
}
__device__ __forceinline__ float frcp(float x) {
    float r;
    asm("rcp.approx.f32 %0, %1;" : "=f"(r) : "f"(x));
    return r;
}
__device__ __forceinline__ void bar256() {
    asm volatile("bar.sync 0, 256;" ::: "memory");
}

#define RED_ROUND(m)                                                          \
  _Pragma("unroll")                                                           \
  for (int k = 0; k < (m); k++) {                                             \
    float a_ = v[k], c_ = v[k + (m)];                                         \
    bool  hi_ = (lane & (m)) != 0;                                            \
    float keep_ = hi_ ? c_ : a_;                                              \
    float send_ = hi_ ? a_ : c_;                                              \
    v[k] = keep_ + __shfl_xor_sync(0xffffffffu, send_, (m));                  \
  }

// normalize by inv, then accumulate one diagonal's matvec contribution
#define BAND_NORM_ACC(d, A11, A12, A21, A22)                                  \
  {                                                                           \
    float a11 = (A11) * inv, a12 = (A12) * inv;                               \
    float a21 = (A21) * inv, a22 = (A22) * inv;                               \
    float4 st_ = s_st[i + (d)];                                               \
    float  csj = s_cs[i + (d)];                                               \
    float muj = st_.x, mlj = st_.y, cuj = st_.z, clj = st_.w;                 \
    nmu = fmaf(a11, muj, nmu); nmu = fmaf(a12, mlj, nmu);                     \
    nml = fmaf(a21, muj, nml); nml = fmaf(a22, mlj, nml);                     \
    ncu = fmaf(a11 * a11, cuj, ncu);                                          \
    ncu = fmaf(2.0f * a11 * a12, csj, ncu);                                   \
    ncu = fmaf(a12 * a12, clj, ncu);                                          \
    ncl = fmaf(a21 * a21, cuj, ncl);                                          \
    ncl = fmaf(2.0f * a21 * a22, csj, ncl);                                   \
    ncl = fmaf(a22 * a22, clj, ncl);                                          \
    ncs = fmaf(a21 * a11, cuj, ncs);                                          \
    ncs = fmaf(fmaf(a22, a11, a21 * a12), csj, ncs);                          \
    ncs = fmaf(a22 * a12, clj, ncs);                                          \
  }

__global__ void __launch_bounds__(256, 1)
rkn_kernel(const float* __restrict__ lobs,   // (B,T,LOD)
           const float* __restrict__ ovars,  // (B,T,LOD)
           const float* __restrict__ imean,  // (B,2*LOD)
           const float* __restrict__ icu,
           const float* __restrict__ icl,
           const float* __restrict__ ics,
           const float* __restrict__ tm11,   // (K,LOD,LOD)
           const float* __restrict__ tm12,
           const float* __restrict__ tm21,
           const float* __restrict__ tm22,
           const float* __restrict__ cw,     // (2*LOD, K)
           const float* __restrict__ cb,     // (K,)
           const float* __restrict__ tcu,
           const float* __restrict__ tcl,
           float* __restrict__ out)
{
    extern __shared__ char smraw[];
    float4* dg   = reinterpret_cast<float4*>(smraw + DG_OFF);
    uint4*  od   = reinterpret_cast<uint4*>(smraw + OD_OFF);
    float4* s_st = reinterpret_cast<float4*>(smraw + ST_OFF);   // [136]
    float*  s_cs = reinterpret_cast<float*>(smraw + CS_OFF);    // [136]
    float*  red  = reinterpret_cast<float*>(smraw + RED_OFF);   // [64]
    float4* p4s  = reinterpret_cast<float4*>(smraw + P4_OFF);   // [2][128]
    float*  p1s  = reinterpret_cast<float*>(smraw + P1_OFF);    // [2][128]

    const int b    = blockIdx.x;
    const int tid  = threadIdx.x;
    const int lane = tid & 31;
    const int warp = tid >> 5;
    const int i    = tid & 127;   // row
    const int h    = tid >> 7;    // half 0/1
    const int k0h  = h << 3;      // this half's logit k-range base

    // ---- prologue: smem tables ----
    for (int r = tid; r < NK * NLOD; r += 256) {
        int k = r >> 7, ii = r & 127;
        long base = ((long)k * NLOD + ii) * NLOD;
        dg[r] = make_float4(__ldg(tm11 + base + ii), __ldg(tm12 + base + ii),
                            __ldg(tm21 + base + ii), __ldg(tm22 + base + ii));
        int j5 = ii + 2, j6 = ii + 3;
        float e11 = 0.f, e12 = 0.f, e21 = 0.f, e22 = 0.f;
        float f11 = 0.f, f12 = 0.f, f21 = 0.f, f22 = 0.f;
        if (j5 < NLOD) {
            e11 = __ldg(tm11 + base + j5); e12 = __ldg(tm12 + base + j5);
            e21 = __ldg(tm21 + base + j5); e22 = __ldg(tm22 + base + j5);
        }
        if (j6 < NLOD) {
            f11 = __ldg(tm11 + base + j6); f12 = __ldg(tm12 + base + j6);
            f21 = __ldg(tm21 + base + j6); f22 = __ldg(tm22 + base + j6);
        }
        od[r] = make_uint4(pk(e11, e12), pk(e21, e22),
                           pk(f11, f12), pk(f21, f22));
    }
    for (int idx = tid; idx < 136; idx += 256) {
        s_st[idx] = make_float4(0.f, 0.f, 0.f, 0.f);
        s_cs[idx] = 0.f;
    }

    const float bbl  = __ldg(cb + (lane & 15));
    const float tcur = __ldg(tcu + i);
    const float tclr = __ldg(tcl + i);

    // this half's 8 softmax-weight columns for row i
    float Wu[8], Wl[8];
    #pragma unroll
    for (int kk = 0; kk < 8; kk++) {
        Wu[kk] = __ldg(cw + i * NK + k0h + kk);
        Wl[kk] = __ldg(cw + (NLOD + i) * NK + k0h + kk);
    }

    // carry partial (registers) + smem mirror for the other half's combine.
    float cmu, cml, ccu, ccl, ccs;
    if (h == 0) {
        cmu = imean[(long)b * 2 * NLOD + i];
        cml = imean[(long)b * 2 * NLOD + NLOD + i];
        ccu = icu[(long)b * NLOD + i] - tcur;
        ccl = icl[(long)b * NLOD + i] - tclr;
        ccs = ics[(long)b * NLOD + i];
    } else {
        cmu = 0.f; cml = 0.f; ccu = 0.f; ccl = 0.f; ccs = 0.f;
    }
    p4s[h * 128 + i] = make_float4(cmu, cml, ccu, ccl);
    p1s[h * 128 + i] = ccs;

    const float* obs_p = lobs  + ((long)b * NT) * NLOD + i;
    const float* ov_p  = ovars + ((long)b * NT) * NLOD + i;
    float obs_r = __ldg(obs_p);
    float ov_r  = __ldg(ov_p);
    obs_p += NLOD; ov_p += NLOD;

    // ---- register tables: 2 diagonals per half ----
    // h0: d0 (j=i-3), d1 (j=i-2)   |   h1: d2 (j=i-1), d4 (j=i+1)
    uint4 Ra[NK];
    {
        const int ja = (h == 0) ? i - 3 : i - 1;
        const int jb = (h == 0) ? i - 2 : i + 1;
        const bool va = (unsigned)ja < (unsigned)NLOD;
        const bool vb = (unsigned)jb < (unsigned)NLOD;
        #pragma unroll
        for (int k = 0; k < NK; k++) {
            long base = ((long)k * NLOD + i) * NLOD;
            float a11 = 0.f, a12 = 0.f, a21 = 0.f, a22 = 0.f;
            float c11 = 0.f, c12 = 0.f, c21 = 0.f, c22 = 0.f;
            if (va) {
                a11 = __ldg(tm11 + base + ja); a12 = __ldg(tm12 + base + ja);
                a21 = __ldg(tm21 + base + ja); a22 = __ldg(tm22 + base + ja);
            }
            if (vb) {
                c11 = __ldg(tm11 + base + jb); c12 = __ldg(tm12 + base + jb);
                c21 = __ldg(tm21 + base + jb); c22 = __ldg(tm22 + base + jb);
            }
            Ra[k] = make_uint4(pk(a11, a12), pk(a21, a22),
                               pk(c11, c12), pk(c21, c22));
        }
    }

    float* out_pm = out;
    float* out_cu = out + (long)NB * NT * 2 * NLOD;
    float* out_cl = out_cu + (long)NB * NT * NLOD;
    float* out_cs = out_cl + (long)NB * NT * NLOD;

    __syncthreads();

    for (int t = 0; t < NT; t++) {
        // ========= phase 1 (both halves, redundant obs update) =========
        float4 pp = p4s[(1 - h) * 128 + i];
        float  ps = p1s[(1 - h) * 128 + i];
        float pmU = cmu + pp.x;
        float pmL = cml + pp.y;
        float cU  = (ccu + pp.z) + tcur;
        float cL  = (ccl + pp.w) + tclr;
        float cS  = ccs + ps;

        float rd    = frcp(cU + ov_r);
        float qu    = cU * rd;
        float ql    = cS * rd;
        float res   = obs_r - pmU;
        float pu    = pmU + qu * res;
        float pl    = pmL + ql * res;
        float cf    = 1.0f - qu;
        float pcu   = cf * cU;
        float pcl   = cL - ql * cS;
        float pcs   = cf * cS;

        if (t + 1 < NT) {
            obs_r = __ldg(obs_p);
            ov_r  = __ldg(ov_p);
            obs_p += NLOD; ov_p += NLOD;
        }

        long obase = (long)b * NT + t;
        if (h == 0) {
            s_st[3 + i] = make_float4(pu, pl, pcu, pcl);
            s_cs[3 + i] = pcs;
            out_pm[obase * 2 * NLOD + i]        = pu;
            out_pm[obase * 2 * NLOD + NLOD + i] = pl;
        } else {
            out_cu[obase * NLOD + i] = pcu;
            out_cl[obase * NLOD + i] = pcl;
            out_cs[obase * NLOD + i] = pcs;
        }

        // logits for this half's 8 k's over 128 rows: value-split FIRST
        // (9 shfls vs 16). After rounds m=4,2,1 lane bits {2,1,0} select k,
        // summed over lane bits 2,1,0; two scalar folds sum bits 3,4.
        float v[8];
        #pragma unroll
        for (int kk = 0; kk < 8; kk++) v[kk] = fmaf(pu, Wu[kk], pl * Wl[kk]);
        RED_ROUND(4)
        RED_ROUND(2)
        RED_ROUND(1)
        v[0] += __shfl_xor_sync(0xffffffffu, v[0], 8);
        v[0] += __shfl_xor_sync(0xffffffffu, v[0], 16);
        if (lane < 8) red[(k0h + lane) * 4 + (warp & 3)] = v[0];
        bar256();   // B1

        // ========= phase 2: softmax (deferred norm) + A-gen + matvec =========
        float w_, s_;
        {
            const float4* red4 = reinterpret_cast<const float4*>(red);
            float4 rp = red4[lane & 15];
            float lg = bbl + ((rp.x + rp.y) + (rp.z + rp.w));
            w_ = __expf(lg);       // unnormalized weight for k = lane&15
            s_ = w_;
            #pragma unroll
            for (int m = 8; m >= 1; m >>= 1)
                s_ += __shfl_xor_sync(0xffffffffu, s_, m);
        }

        float nmu = 0.f, nml = 0.f, ncu = 0.f, ncl = 0.f, ncs = 0.f;

        if (h == 0) {
            // regs: d0,d1 bf16; smem: fp32 diag
            float D11 = 0.f, D12 = 0.f, D21 = 0.f, D22 = 0.f;
            unsigned long long P0 = 0ull, Q0 = 0ull, P1 = 0ull, Q1 = 0ull;
            #pragma unroll
            for (int k = 0; k < NK; k++) {
                float a = __shfl_sync(0xffffffffu, w_, k);
                unsigned long long a2 = dup2(a);
                uint4 r = Ra[k];
                float4 gv = dg[k * NLOD + i];
                pair_fma(P0, r.x, a2);
                pair_fma(Q0, r.y, a2);
                pair_fma(P1, r.z, a2);
                pair_fma(Q1, r.w, a2);
                D11 = fmaf(a, gv.x, D11);
                D12 = fmaf(a, gv.y, D12);
                D21 = fmaf(a, gv.z, D21);
                D22 = fmaf(a, gv.w, D22);
            }
            const float inv = frcp(s_);
            float x, y, z, w2;
            unpk2(P0, x, y); unpk2(Q0, z, w2);
            BAND_NORM_ACC(0, x, y, z, w2)
            unpk2(P1, x, y); unpk2(Q1, z, w2);
            BAND_NORM_ACC(1, x, y, z, w2)
            {   // diagonal: A = D*inv + I
                float a11 = fmaf(D11, inv, 1.0f), a12 = D12 * inv;
                float a21 = D21 * inv, a22 = fmaf(D22, inv, 1.0f);
                float4 st_ = s_st[i + 3];
                float  csj = s_cs[i + 3];
                float muj = st_.x, mlj = st_.y, cuj = st_.z, clj = st_.w;
                nmu = fmaf(a11, muj, nmu); nmu = fmaf(a12, mlj, nmu);
                nml = fmaf(a21, muj, nml); nml = fmaf(a22, mlj, nml);
                ncu = fmaf(a11 * a11, cuj, ncu);
                ncu = fmaf(2.0f * a11 * a12, csj, ncu);
                ncu = fmaf(a12 * a12, clj, ncu);
                ncl = fmaf(a21 * a21, cuj, ncl);
                ncl = fmaf(2.0f * a21 * a22, csj, ncl);
                ncl = fmaf(a22 * a22, clj, ncl);
                ncs = fmaf(a21 * a11, cuj, ncs);
                ncs = fmaf(fmaf(a22, a11, a21 * a12), csj, ncs);
                ncs = fmaf(a22 * a12, clj, ncs);
            }
        } else {
            // regs: d2,d4 bf16; smem: d5,d6 bf16
            unsigned long long P2 = 0ull, Q2 = 0ull, P4 = 0ull, Q4 = 0ull;
            unsigned long long P5 = 0ull, Q5 = 0ull, P6 = 0ull, Q6 = 0ull;
            #pragma unroll
            for (int k = 0; k < NK; k++) {
                unsigned long long a2 = dup2(__shfl_sync(0xffffffffu, w_, k));
                uint4 r = Ra[k];
                uint4 ro = od[k * NLOD + i];
                pair_fma(P2, r.x, a2);
                pair_fma(Q2, r.y, a2);
                pair_fma(P4, r.z, a2);
                pair_fma(Q4, r.w, a2);
                pair_fma(P5, ro.x, a2);
                pair_fma(Q5, ro.y, a2);
                pair_fma(P6, ro.z, a2);
                pair_fma(Q6, ro.w, a2);
            }
            const float inv = frcp(s_);
            float x, y, z, w2;
            unpk2(P2, x, y); unpk2(Q2, z, w2);
            BAND_NORM_ACC(2, x, y, z, w2)
            unpk2(P4, x, y); unpk2(Q4, z, w2);
            BAND_NORM_ACC(4, x, y, z, w2)
            unpk2(P5, x, y); unpk2(Q5, z, w2);
            BAND_NORM_ACC(5, x, y, z, w2)
            unpk2(P6, x, y); unpk2(Q6, z, w2);
            BAND_NORM_ACC(6, x, y, z, w2)
        }

        cmu = nmu; cml = nml; ccu = ncu; ccl = ncl; ccs = ncs;
        p4s[h * 128 + i] = make_float4(nmu, nml, ncu, ncl);
        p1s[h * 128 + i] = ncs;
        bar256();   // B2
    }
}

extern "C" void kernel_launch(void* const* d_in, const int* in_sizes, int n_in,
                              void* d_out, int out_size)
{
    (void)in_sizes; (void)n_in; (void)out_size;
    const float* lobs  = (const float*)d_in[0];
    const float* ovars = (const float*)d_in[1];
    const float* imean = (const float*)d_in[2];
    const float* icu   = (const float*)d_in[3];
    const float* icl   = (const float*)d_in[4];
    const float* ics   = (const float*)d_in[5];
    const float* tm11  = (const float*)d_in[6];
    const float* tm12  = (const float*)d_in[7];
    const float* tm21  = (const float*)d_in[8];
    const float* tm22  = (const float*)d_in[9];
    const float* cw    = (const float*)d_in[10];
    const float* cb    = (const float*)d_in[11];
    const float* tcu   = (const float*)d_in[12];
    const float* tcl   = (const float*)d_in[13];
    float* out = (float*)d_out;

    cudaFuncSetAttribute(rkn_kernel,
                         cudaFuncAttributeMaxDynamicSharedMemorySize, SMEM_BYTES);

    rkn_kernel<<<NB, 256, SMEM_BYTES>>>(lobs, ovars, imean, icu, icl, ics,
                                        tm11, tm12, tm21, tm22,
                                        cw, cb, tcu, tcl, out);
}